// round 3
// baseline (speedup 1.0000x reference)
#include <cuda_runtime.h>
#include <cuda_bf16.h>
#include <stdint.h>

// Problem constants (dataset-fixed; scratch arrays sized to these)
#define NN 100000
#define EE 3200000
#define IN_C 128
#define HID_C 256
#define OUT_C 64

// ---------------- device scratch (no dynamic allocation allowed) ----------------
__device__ int   g_row[EE];                 // edge source (int32, converted)
__device__ int   g_col[EE];                 // edge target (int32, converted)
__device__ int   g_is64[1];                 // dtype flag from detector
__device__ float g_deg[NN];                 // degree -> dinv (in place)
__device__ float g_nw[EE];                  // normalized edge weights
__device__ float g_tx1[NN * IN_C];          // L x              [N,128]
__device__ float g_s[NN * IN_C];            // L (L x)          [N,128]
__device__ float g_h[NN * HID_C];           // relu(layer1)     [N,256]
__device__ float g_z[NN * 3 * OUT_C];       // h @ [W2_0|W2_1|W2_2]  [N,192]
__device__ float g_u[NN * 2 * OUT_C];       // [L z1 | L z2]    [N,128]
__device__ float g_w1c[(3 * IN_C) * HID_C]; // folded layer-1 weight [384,256]
__device__ float g_w2c[HID_C * 3 * OUT_C];  // rearranged layer-2 weight [256,192]

// ---------------- helpers ----------------
__device__ __forceinline__ void red_add_f32x4(float* addr, float4 v) {
    asm volatile("red.global.add.v4.f32 [%0], {%1,%2,%3,%4};"
                 :: "l"(addr), "f"(v.x), "f"(v.y), "f"(v.z), "f"(v.w) : "memory");
}
__device__ __forceinline__ void red_add_f32x2(float* addr, float2 v) {
    asm volatile("red.global.add.v2.f32 [%0], {%1,%2};"
                 :: "l"(addr), "f"(v.x), "f"(v.y) : "memory");
}

// ---------------- edge index dtype detection + conversion ----------------
// If the buffer truly holds int64 indices, every 8-byte word is in [0, N).
// If it holds int32 (JAX x64-disabled downgrade), an 8-byte read fuses two
// indices -> value >= 2^32 whenever the odd-position index != 0.
__global__ void k_detect(const void* ei, int E, int n, int* flag) {
    const long long* p = (const long long*)ei;
    int cnt = E < 1024 ? E : 1024;
    int ok64 = 1;
    for (int i = 0; i < cnt; i++) {
        long long v = p[i];
        if (v < 0 || v >= n) { ok64 = 0; break; }
    }
    flag[0] = ok64;
}

__global__ void k_cvt(const void* ei, int E, const int* flag,
                      int* __restrict__ row, int* __restrict__ col) {
    int e = blockIdx.x * blockDim.x + threadIdx.x;
    if (e >= E) return;
    if (flag[0]) {
        const long long* p = (const long long*)ei;
        row[e] = (int)p[e];
        col[e] = (int)p[(long long)E + e];
    } else {
        const int* p = (const int*)ei;
        row[e] = p[e];
        col[e] = p[E + e];
    }
}

// ---------------- graph preprocessing ----------------
__global__ void k_deg(const int* __restrict__ row, const float* __restrict__ w,
                      float* __restrict__ deg, int E) {
    int e = blockIdx.x * blockDim.x + threadIdx.x;
    if (e < E) atomicAdd(&deg[row[e]], w[e]);
}

__global__ void k_dinv(float* __restrict__ deg, int n) {
    int i = blockIdx.x * blockDim.x + threadIdx.x;
    if (i < n) {
        float d = deg[i];
        deg[i] = (d > 0.0f) ? rsqrtf(d) : 0.0f;
    }
}

__global__ void k_nw(const int* __restrict__ row, const int* __restrict__ col,
                     const float* __restrict__ w,
                     const float* __restrict__ dinv, float* __restrict__ nw, int E) {
    int e = blockIdx.x * blockDim.x + threadIdx.x;
    if (e < E) {
        nw[e] = -(dinv[row[e]] * w[e] * dinv[col[e]]);
    }
}

// Fold layer-1 weights: rows 0-127 = W1[0]-W1[2]; 128-255 = W1[1]; 256-383 = 2*W1[2]
__global__ void k_w1c(const float* __restrict__ W1, float* __restrict__ w1c) {
    int i = blockIdx.x * blockDim.x + threadIdx.x;
    const int total = 3 * IN_C * HID_C;
    if (i >= total) return;
    int r = i / HID_C;
    int j = i - r * HID_C;
    float v;
    if (r < IN_C) {
        v = W1[(size_t)0 * IN_C * HID_C + r * HID_C + j] -
            W1[(size_t)2 * IN_C * HID_C + r * HID_C + j];
    } else if (r < 2 * IN_C) {
        v = W1[(size_t)1 * IN_C * HID_C + (r - IN_C) * HID_C + j];
    } else {
        v = 2.0f * W1[(size_t)2 * IN_C * HID_C + (r - 2 * IN_C) * HID_C + j];
    }
    w1c[i] = v;
}

// Rearrange layer-2 weights: w2c[c][k*64+o] = W2[k][c][o]   (shape [256,192])
__global__ void k_w2c(const float* __restrict__ W2, float* __restrict__ w2c) {
    int i = blockIdx.x * blockDim.x + threadIdx.x;
    const int total = HID_C * 3 * OUT_C;
    if (i >= total) return;
    int c = i / (3 * OUT_C);
    int t = i - c * (3 * OUT_C);
    int k = t / OUT_C;
    int o = t - k * OUT_C;
    w2c[i] = W2[(size_t)k * HID_C * OUT_C + c * OUT_C + o];
}

// ---------------- SpMM: dst[row,:] += scale*nw[e]*src[col, soff:soff+C] ----------------
// 128-channel version: one warp per edge, float4 per lane.
__global__ void spmm128(const int* __restrict__ row, const int* __restrict__ col,
                        const float* __restrict__ nw,
                        const float* __restrict__ src, int sstride, int soff,
                        float* __restrict__ dst, int dstride, float scale, int E) {
    int wrp = (blockIdx.x * blockDim.x + threadIdx.x) >> 5;
    int lane = threadIdx.x & 31;
    if (wrp >= E) return;
    float nv = nw[wrp] * scale;
    if (nv == 0.0f) return;
    int r = row[wrp];
    int c = col[wrp];
    const float4* s4 = (const float4*)(src + (size_t)c * sstride + soff);
    float4 v = __ldg(&s4[lane]);
    v.x *= nv; v.y *= nv; v.z *= nv; v.w *= nv;
    red_add_f32x4(dst + (size_t)r * dstride + lane * 4, v);
}

// 64-channel version: one warp per edge, float2 per lane.
__global__ void spmm64(const int* __restrict__ row, const int* __restrict__ col,
                       const float* __restrict__ nw,
                       const float* __restrict__ src, int sstride, int soff,
                       float* __restrict__ dst, int dstride, float scale, int E) {
    int wrp = (blockIdx.x * blockDim.x + threadIdx.x) >> 5;
    int lane = threadIdx.x & 31;
    if (wrp >= E) return;
    float nv = nw[wrp] * scale;
    if (nv == 0.0f) return;
    int r = row[wrp];
    int c = col[wrp];
    const float2* s2 = (const float2*)(src + (size_t)c * sstride + soff);
    float2 v = __ldg(&s2[lane]);
    v.x *= nv; v.y *= nv;
    red_add_f32x2(dst + (size_t)r * dstride + lane * 2, v);
}

// ---------------- SGEMM: C[M,Ncols] = [A0|A1|A2](each partK cols, stride lda) @ B[K,Ncols] ----------------
#define BM 128
#define BN 64
#define BK 16
#define GEMM_THREADS 256

__global__ __launch_bounds__(GEMM_THREADS)
void gemm_kernel(const float* __restrict__ A0, const float* __restrict__ A1,
                 const float* __restrict__ A2, int lda, int partK,
                 const float* __restrict__ B, int ldb,
                 float* __restrict__ C, int ldc,
                 const float* __restrict__ bias,
                 int M, int Ncols, int K, int doRelu) {
    __shared__ float As[BK][BM + 4];
    __shared__ float Bs[BK][BN + 4];

    const int m0 = blockIdx.x * BM;
    const int n0 = blockIdx.y * BN;
    const int tid = threadIdx.x;
    const int tr = tid >> 4;          // 0..15 -> 8 rows each
    const int tc = tid & 15;          // 0..15 -> 4 cols each

    // A load mapping: 2 x float4 along K per thread
    const int amr = tid >> 2;         // 0..63 (row within tile; +64 for second)
    const int ak4 = (tid & 3) * 4;    // k offset 0,4,8,12
    // B load mapping: 1 x float4 per thread
    const int bk = tid >> 4;          // 0..15
    const int bn = (tid & 15) * 4;    // 0..60

    float acc[8][4];
#pragma unroll
    for (int i = 0; i < 8; i++)
#pragma unroll
        for (int j = 0; j < 4; j++) acc[i][j] = 0.0f;

    const float* parts[3] = {A0, A1, A2};

    for (int k0 = 0; k0 < K; k0 += BK) {
        const int part = k0 / partK;
        const float* Ap = parts[part];
        const int kloc = k0 - part * partK;

#pragma unroll
        for (int i = 0; i < 2; i++) {
            int m = amr + i * 64;
            int gm = m0 + m;
            float4 v = make_float4(0.f, 0.f, 0.f, 0.f);
            if (gm < M) v = *(const float4*)(Ap + (size_t)gm * lda + kloc + ak4);
            As[ak4 + 0][m] = v.x;
            As[ak4 + 1][m] = v.y;
            As[ak4 + 2][m] = v.z;
            As[ak4 + 3][m] = v.w;
        }
        {
            float4 v = make_float4(0.f, 0.f, 0.f, 0.f);
            if (n0 + bn < Ncols) v = *(const float4*)(B + (size_t)(k0 + bk) * ldb + n0 + bn);
            *(float4*)&Bs[bk][bn] = v;
        }
        __syncthreads();

#pragma unroll
        for (int kk = 0; kk < BK; kk++) {
            float4 a0 = *(const float4*)&As[kk][tr * 8];
            float4 a1 = *(const float4*)&As[kk][tr * 8 + 4];
            float4 b  = *(const float4*)&Bs[kk][tc * 4];
            float a[8] = {a0.x, a0.y, a0.z, a0.w, a1.x, a1.y, a1.z, a1.w};
            float bv[4] = {b.x, b.y, b.z, b.w};
#pragma unroll
            for (int i = 0; i < 8; i++)
#pragma unroll
                for (int j = 0; j < 4; j++)
                    acc[i][j] = fmaf(a[i], bv[j], acc[i][j]);
        }
        __syncthreads();
    }

    // epilogue
    const int gn = n0 + tc * 4;
    float4 bb = make_float4(0.f, 0.f, 0.f, 0.f);
    if (bias != nullptr && gn < Ncols) bb = *(const float4*)(bias + gn);
#pragma unroll
    for (int i = 0; i < 8; i++) {
        int gm = m0 + tr * 8 + i;
        if (gm < M && gn < Ncols) {
            float4 v = make_float4(acc[i][0] + bb.x, acc[i][1] + bb.y,
                                   acc[i][2] + bb.z, acc[i][3] + bb.w);
            if (doRelu) {
                v.x = fmaxf(v.x, 0.f); v.y = fmaxf(v.y, 0.f);
                v.z = fmaxf(v.z, 0.f); v.w = fmaxf(v.w, 0.f);
            }
            *(float4*)(C + (size_t)gm * ldc + gn) = v;
        }
    }
}

// out = z0 - z2 + u[:,0:64] + b2   (then spmm64 adds 2*L(u[:,64:128]))
__global__ void k_outinit(const float* __restrict__ z, const float* __restrict__ u,
                          const float* __restrict__ b2, float* __restrict__ out, int n) {
    int i = blockIdx.x * blockDim.x + threadIdx.x;
    int total = n * OUT_C;
    if (i >= total) return;
    int nn = i / OUT_C;
    int o = i - nn * OUT_C;
    out[i] = z[(size_t)nn * 192 + o] - z[(size_t)nn * 192 + 128 + o]
           + u[(size_t)nn * 128 + o] + b2[o];
}

// ---------------- launch ----------------
extern "C" void kernel_launch(void* const* d_in, const int* in_sizes, int n_in,
                              void* d_out, int out_size) {
    const float* x  = (const float*)d_in[0];
    const void*  ei = d_in[1];                 // int32 or int64, detected on device
    const float* ew = (const float*)d_in[2];
    const float* W1 = (const float*)d_in[3];
    const float* b1 = (const float*)d_in[4];
    const float* W2 = (const float*)d_in[5];
    const float* b2 = (const float*)d_in[6];
    float* out = (float*)d_out;

    int N = in_sizes[0] / IN_C;   // 100000
    int E = in_sizes[2];          // 3200000
    if (N > NN) N = NN;
    if (E > EE) E = EE;

    int *row, *col, *flag;
    float *deg, *nw, *tx1, *s, *h, *z, *u, *w1c, *w2c;
    cudaGetSymbolAddress((void**)&row,  g_row);
    cudaGetSymbolAddress((void**)&col,  g_col);
    cudaGetSymbolAddress((void**)&flag, g_is64);
    cudaGetSymbolAddress((void**)&deg,  g_deg);
    cudaGetSymbolAddress((void**)&nw,   g_nw);
    cudaGetSymbolAddress((void**)&tx1,  g_tx1);
    cudaGetSymbolAddress((void**)&s,    g_s);
    cudaGetSymbolAddress((void**)&h,    g_h);
    cudaGetSymbolAddress((void**)&z,    g_z);
    cudaGetSymbolAddress((void**)&u,    g_u);
    cudaGetSymbolAddress((void**)&w1c,  g_w1c);
    cudaGetSymbolAddress((void**)&w2c,  g_w2c);

    // zero accumulators
    cudaMemsetAsync(deg, 0, (size_t)N * sizeof(float), 0);
    cudaMemsetAsync(tx1, 0, (size_t)N * IN_C * sizeof(float), 0);
    cudaMemsetAsync(s,   0, (size_t)N * IN_C * sizeof(float), 0);
    cudaMemsetAsync(u,   0, (size_t)N * 2 * OUT_C * sizeof(float), 0);

    const int T = 256;

    // edge index dtype detection + conversion to int32
    k_detect<<<1, 1>>>(ei, E, N, flag);
    k_cvt<<<(E + T - 1) / T, T>>>(ei, E, flag, row, col);

    // normalization
    k_deg<<<(E + T - 1) / T, T>>>(row, ew, deg, E);
    k_dinv<<<(N + T - 1) / T, T>>>(deg, N);
    k_nw<<<(E + T - 1) / T, T>>>(row, col, ew, deg, nw, E);

    // weight folding
    k_w1c<<<(3 * IN_C * HID_C + T - 1) / T, T>>>(W1, w1c);
    k_w2c<<<(HID_C * 3 * OUT_C + T - 1) / T, T>>>(W2, w2c);

    const int spmmBlocks = (E + 7) / 8;   // 8 warps per 256-thread block, 1 warp/edge

    // Layer 1 Chebyshev terms
    spmm128<<<spmmBlocks, T>>>(row, col, nw, x,   IN_C, 0, tx1, IN_C, 1.0f, E);  // tx1 = L x
    spmm128<<<spmmBlocks, T>>>(row, col, nw, tx1, IN_C, 0, s,   IN_C, 1.0f, E);  // s   = L tx1

    // h = relu([x|tx1|s] @ w1c + b1)
    {
        dim3 grid((N + BM - 1) / BM, HID_C / BN);
        gemm_kernel<<<grid, GEMM_THREADS>>>(x, tx1, s, IN_C, IN_C,
                                            w1c, HID_C, h, HID_C, b1,
                                            N, HID_C, 3 * IN_C, 1);
    }

    // z = h @ w2c   [N,192]
    {
        dim3 grid((N + BM - 1) / BM, (3 * OUT_C) / BN);
        gemm_kernel<<<grid, GEMM_THREADS>>>(h, h, h, HID_C, HID_C,
                                            w2c, 3 * OUT_C, z, 3 * OUT_C, nullptr,
                                            N, 3 * OUT_C, HID_C, 0);
    }

    // u = L [z1|z2]  (cols 64..191 of z)
    spmm128<<<spmmBlocks, T>>>(row, col, nw, z, 3 * OUT_C, OUT_C, u, 2 * OUT_C, 1.0f, E);

    // out = z0 - z2 + u[:,0:64] + b2
    k_outinit<<<(N * OUT_C + T - 1) / T, T>>>(z, u, b2, out, N);

    // out += 2 * L(u[:,64:128])
    spmm64<<<spmmBlocks, T>>>(row, col, nw, u, 2 * OUT_C, OUT_C, out, OUT_C, 2.0f, E);
}

// round 5
// speedup vs baseline: 2.4033x; 2.4033x over previous
#include <cuda_runtime.h>
#include <cuda_bf16.h>
#include <stdint.h>

// Problem constants (dataset-fixed; scratch arrays sized to these)
#define NN 100000
#define EE 3200000
#define IN_C 128
#define HID_C 256
#define OUT_C 64
#define SCAN_B 256
#define NB_MAX 512   // ceil(NN/SCAN_B) = 391 <= 512

// ---------------- device scratch (no dynamic allocation allowed) ----------------
__device__ int   g_row[EE];                 // edge source (int32, converted)
__device__ int   g_col[EE];                 // edge target (int32, converted)
__device__ int   g_is64[1];                 // dtype flag from detector
__device__ float g_deg[NN];                 // weighted degree -> dinv (in place)
__device__ int   g_cnt[NN];                 // edge count per row
__device__ int   g_rowptr[NN];              // CSR row offsets (exclusive scan of cnt)
__device__ int   g_cursor[NN];              // scatter cursors
__device__ int   g_bsum[NB_MAX];            // scan block sums
__device__ int   g_pcol[EE];                // CSR-permuted cols
__device__ float g_pnw[EE];                 // CSR-permuted normalized weights
__device__ float g_tx1[NN * IN_C];          // L x              [N,128]
__device__ float g_s[NN * IN_C];            // L (L x)          [N,128]
__device__ float g_h[NN * HID_C];           // relu(layer1)     [N,256]
__device__ float g_z[NN * 3 * OUT_C];       // h @ [W2_0|W2_1|W2_2]  [N,192]
__device__ float g_u[NN * 2 * OUT_C];       // [L z1 | L z2]    [N,128]
__device__ float g_w1c[(3 * IN_C) * HID_C]; // folded layer-1 weight [384,256]
__device__ float g_w2c[HID_C * 3 * OUT_C];  // rearranged layer-2 weight [256,192]

// ---------------- edge index dtype detection + conversion ----------------
__global__ void k_detect(const void* ei, int E, int n, int* flag) {
    const long long* p = (const long long*)ei;
    int cnt = E < 1024 ? E : 1024;
    int ok64 = 1;
    for (int i = 0; i < cnt; i++) {
        long long v = p[i];
        if (v < 0 || v >= n) { ok64 = 0; break; }
    }
    flag[0] = ok64;
}

__global__ void k_cvt(const void* ei, int E, const int* flag,
                      int* __restrict__ row, int* __restrict__ col) {
    int e = blockIdx.x * blockDim.x + threadIdx.x;
    if (e >= E) return;
    if (flag[0]) {
        const long long* p = (const long long*)ei;
        row[e] = (int)p[e];
        col[e] = (int)p[(long long)E + e];
    } else {
        const int* p = (const int*)ei;
        row[e] = p[e];
        col[e] = p[E + e];
    }
}

// ---------------- graph preprocessing ----------------
// weighted degree (for normalization) + edge count (for CSR) in one pass
__global__ void k_deg2(const int* __restrict__ row, const float* __restrict__ w,
                       float* __restrict__ deg, int* __restrict__ cnt, int E) {
    int e = blockIdx.x * blockDim.x + threadIdx.x;
    if (e < E) {
        int r = row[e];
        atomicAdd(&deg[r], w[e]);
        atomicAdd(&cnt[r], 1);
    }
}

__global__ void k_dinv(float* __restrict__ deg, int n) {
    int i = blockIdx.x * blockDim.x + threadIdx.x;
    if (i < n) {
        float d = deg[i];
        deg[i] = (d > 0.0f) ? rsqrtf(d) : 0.0f;
    }
}

// ---- 3-kernel exclusive scan of cnt -> rowptr ----
__global__ void k_scan1(const int* __restrict__ cnt, int* __restrict__ rowptr,
                        int* __restrict__ bsum, int n) {
    __shared__ int sm[SCAN_B];
    int t = threadIdx.x;
    int i = blockIdx.x * SCAN_B + t;
    int v = (i < n) ? cnt[i] : 0;
    int orig = v;
#pragma unroll
    for (int d = 1; d < SCAN_B; d <<= 1) {
        sm[t] = v; __syncthreads();
        int a = (t >= d) ? sm[t - d] : 0; __syncthreads();
        v += a;
    }
    if (i < n) rowptr[i] = v - orig;       // exclusive within block
    if (t == SCAN_B - 1) bsum[blockIdx.x] = v;  // block total
}

__global__ void k_scan2(int* __restrict__ bsum, int nb) {
    __shared__ int sm[NB_MAX];
    int t = threadIdx.x;   // blockDim = NB_MAX
    int v = (t < nb) ? bsum[t] : 0;
    int orig = v;
#pragma unroll
    for (int d = 1; d < NB_MAX; d <<= 1) {
        sm[t] = v; __syncthreads();
        int a = (t >= d) ? sm[t - d] : 0; __syncthreads();
        v += a;
    }
    if (t < nb) bsum[t] = v - orig;        // exclusive block offsets
}

__global__ void k_scan3(int* __restrict__ rowptr, int* __restrict__ cursor,
                        const int* __restrict__ bsum, int n) {
    int i = blockIdx.x * SCAN_B + threadIdx.x;
    if (i < n) {
        int v = rowptr[i] + bsum[blockIdx.x];
        rowptr[i] = v;
        cursor[i] = v;
    }
}

// scatter edges into CSR order, computing normalized weight inline
__global__ void k_scatter(const int* __restrict__ row, const int* __restrict__ col,
                          const float* __restrict__ w, const float* __restrict__ dinv,
                          int* __restrict__ cursor,
                          int* __restrict__ pcol, float* __restrict__ pnw, int E) {
    int e = blockIdx.x * blockDim.x + threadIdx.x;
    if (e >= E) return;
    int r = row[e];
    int c = col[e];
    int pos = atomicAdd(&cursor[r], 1);
    pcol[pos] = c;
    pnw[pos] = -(dinv[r] * w[e] * dinv[c]);
}

// ---------------- weight folding ----------------
__global__ void k_w1c(const float* __restrict__ W1, float* __restrict__ w1c) {
    int i = blockIdx.x * blockDim.x + threadIdx.x;
    const int total = 3 * IN_C * HID_C;
    if (i >= total) return;
    int r = i / HID_C;
    int j = i - r * HID_C;
    float v;
    if (r < IN_C) {
        v = W1[(size_t)0 * IN_C * HID_C + r * HID_C + j] -
            W1[(size_t)2 * IN_C * HID_C + r * HID_C + j];
    } else if (r < 2 * IN_C) {
        v = W1[(size_t)1 * IN_C * HID_C + (r - IN_C) * HID_C + j];
    } else {
        v = 2.0f * W1[(size_t)2 * IN_C * HID_C + (r - 2 * IN_C) * HID_C + j];
    }
    w1c[i] = v;
}

__global__ void k_w2c(const float* __restrict__ W2, float* __restrict__ w2c) {
    int i = blockIdx.x * blockDim.x + threadIdx.x;
    const int total = HID_C * 3 * OUT_C;
    if (i >= total) return;
    int c = i / (3 * OUT_C);
    int t = i - c * (3 * OUT_C);
    int k = t / OUT_C;
    int o = t - k * OUT_C;
    w2c[i] = W2[(size_t)k * HID_C * OUT_C + c * OUT_C + o];
}

// ---------------- CSR SpMM: dst[r,:] = sum_e nw[e] * src[col[e], soff:soff+128] ----------------
// One warp per row, float4 per lane, register accumulation, single store.
__global__ void spmm_csr128(const int* __restrict__ rowptr, const int* __restrict__ cnt,
                            const int* __restrict__ pcol, const float* __restrict__ pnw,
                            const float* __restrict__ src, int sstride4, int soff4,
                            float* __restrict__ dst, int dstride4, int N) {
    int r = (blockIdx.x * blockDim.x + threadIdx.x) >> 5;
    int lane = threadIdx.x & 31;
    if (r >= N) return;
    int e = rowptr[r];
    int end = e + cnt[r];
    float4 acc = make_float4(0.f, 0.f, 0.f, 0.f);
    const float4* s4 = (const float4*)src;
    // unroll-2 for MLP
    for (; e + 1 < end; e += 2) {
        int c0 = __ldg(&pcol[e]);     float n0 = __ldg(&pnw[e]);
        int c1 = __ldg(&pcol[e + 1]); float n1 = __ldg(&pnw[e + 1]);
        float4 v0 = __ldg(&s4[(size_t)c0 * sstride4 + soff4 + lane]);
        float4 v1 = __ldg(&s4[(size_t)c1 * sstride4 + soff4 + lane]);
        acc.x = fmaf(n0, v0.x, acc.x); acc.y = fmaf(n0, v0.y, acc.y);
        acc.z = fmaf(n0, v0.z, acc.z); acc.w = fmaf(n0, v0.w, acc.w);
        acc.x = fmaf(n1, v1.x, acc.x); acc.y = fmaf(n1, v1.y, acc.y);
        acc.z = fmaf(n1, v1.z, acc.z); acc.w = fmaf(n1, v1.w, acc.w);
    }
    if (e < end) {
        int c0 = __ldg(&pcol[e]); float n0 = __ldg(&pnw[e]);
        float4 v0 = __ldg(&s4[(size_t)c0 * sstride4 + soff4 + lane]);
        acc.x = fmaf(n0, v0.x, acc.x); acc.y = fmaf(n0, v0.y, acc.y);
        acc.z = fmaf(n0, v0.z, acc.z); acc.w = fmaf(n0, v0.w, acc.w);
    }
    ((float4*)dst)[(size_t)r * dstride4 + lane] = acc;
}

// Final fused: out[r,:] = z0[r] - z2[r] + u_lo[r] + b2 + 2 * sum_e nw[e]*u_hi[col[e]]
__global__ void spmm_csr64_final(const int* __restrict__ rowptr, const int* __restrict__ cnt,
                                 const int* __restrict__ pcol, const float* __restrict__ pnw,
                                 const float* __restrict__ u, const float* __restrict__ z,
                                 const float* __restrict__ b2,
                                 float* __restrict__ out, int N) {
    int r = (blockIdx.x * blockDim.x + threadIdx.x) >> 5;
    int lane = threadIdx.x & 31;
    if (r >= N) return;
    int e = rowptr[r];
    int end = e + cnt[r];
    float2 acc = make_float2(0.f, 0.f);
    for (; e + 1 < end; e += 2) {
        int c0 = __ldg(&pcol[e]);     float n0 = __ldg(&pnw[e]);
        int c1 = __ldg(&pcol[e + 1]); float n1 = __ldg(&pnw[e + 1]);
        float2 v0 = __ldg((const float2*)(u + (size_t)c0 * 128 + 64 + lane * 2));
        float2 v1 = __ldg((const float2*)(u + (size_t)c1 * 128 + 64 + lane * 2));
        acc.x = fmaf(n0, v0.x, acc.x); acc.y = fmaf(n0, v0.y, acc.y);
        acc.x = fmaf(n1, v1.x, acc.x); acc.y = fmaf(n1, v1.y, acc.y);
    }
    if (e < end) {
        int c0 = __ldg(&pcol[e]); float n0 = __ldg(&pnw[e]);
        float2 v0 = __ldg((const float2*)(u + (size_t)c0 * 128 + 64 + lane * 2));
        acc.x = fmaf(n0, v0.x, acc.x); acc.y = fmaf(n0, v0.y, acc.y);
    }
    int o = lane * 2;
    float2 z0 = *(const float2*)(z + (size_t)r * 192 + o);
    float2 z2 = *(const float2*)(z + (size_t)r * 192 + 128 + o);
    float2 ul = *(const float2*)(u + (size_t)r * 128 + o);
    float2 bb = *(const float2*)(b2 + o);
    float2 res;
    res.x = z0.x - z2.x + ul.x + bb.x + 2.0f * acc.x;
    res.y = z0.y - z2.y + ul.y + bb.y + 2.0f * acc.y;
    *(float2*)(out + (size_t)r * 64 + o) = res;
}

// ---------------- SGEMM: C[M,Ncols] = [A0|A1|A2](each partK cols, stride lda) @ B[K,Ncols] ----------------
#define BM 128
#define BN 64
#define BK 16
#define GEMM_THREADS 256

__global__ __launch_bounds__(GEMM_THREADS)
void gemm_kernel(const float* __restrict__ A0, const float* __restrict__ A1,
                 const float* __restrict__ A2, int lda, int partK,
                 const float* __restrict__ B, int ldb,
                 float* __restrict__ C, int ldc,
                 const float* __restrict__ bias,
                 int M, int Ncols, int K, int doRelu) {
    __shared__ float As[BK][BM + 4];
    __shared__ float Bs[BK][BN + 4];

    const int m0 = blockIdx.x * BM;
    const int n0 = blockIdx.y * BN;
    const int tid = threadIdx.x;
    const int tr = tid >> 4;
    const int tc = tid & 15;

    const int amr = tid >> 2;
    const int ak4 = (tid & 3) * 4;
    const int bk = tid >> 4;
    const int bn = (tid & 15) * 4;

    float acc[8][4];
#pragma unroll
    for (int i = 0; i < 8; i++)
#pragma unroll
        for (int j = 0; j < 4; j++) acc[i][j] = 0.0f;

    const float* parts[3] = {A0, A1, A2};

    for (int k0 = 0; k0 < K; k0 += BK) {
        const int part = k0 / partK;
        const float* Ap = parts[part];
        const int kloc = k0 - part * partK;

#pragma unroll
        for (int i = 0; i < 2; i++) {
            int m = amr + i * 64;
            int gm = m0 + m;
            float4 v = make_float4(0.f, 0.f, 0.f, 0.f);
            if (gm < M) v = *(const float4*)(Ap + (size_t)gm * lda + kloc + ak4);
            As[ak4 + 0][m] = v.x;
            As[ak4 + 1][m] = v.y;
            As[ak4 + 2][m] = v.z;
            As[ak4 + 3][m] = v.w;
        }
        {
            float4 v = make_float4(0.f, 0.f, 0.f, 0.f);
            if (n0 + bn < Ncols) v = *(const float4*)(B + (size_t)(k0 + bk) * ldb + n0 + bn);
            *(float4*)&Bs[bk][bn] = v;
        }
        __syncthreads();

#pragma unroll
        for (int kk = 0; kk < BK; kk++) {
            float4 a0 = *(const float4*)&As[kk][tr * 8];
            float4 a1 = *(const float4*)&As[kk][tr * 8 + 4];
            float4 b  = *(const float4*)&Bs[kk][tc * 4];
            float a[8] = {a0.x, a0.y, a0.z, a0.w, a1.x, a1.y, a1.z, a1.w};
            float bv[4] = {b.x, b.y, b.z, b.w};
#pragma unroll
            for (int i = 0; i < 8; i++)
#pragma unroll
                for (int j = 0; j < 4; j++)
                    acc[i][j] = fmaf(a[i], bv[j], acc[i][j]);
        }
        __syncthreads();
    }

    const int gn = n0 + tc * 4;
    float4 bb = make_float4(0.f, 0.f, 0.f, 0.f);
    if (bias != nullptr && gn < Ncols) bb = *(const float4*)(bias + gn);
#pragma unroll
    for (int i = 0; i < 8; i++) {
        int gm = m0 + tr * 8 + i;
        if (gm < M && gn < Ncols) {
            float4 v = make_float4(acc[i][0] + bb.x, acc[i][1] + bb.y,
                                   acc[i][2] + bb.z, acc[i][3] + bb.w);
            if (doRelu) {
                v.x = fmaxf(v.x, 0.f); v.y = fmaxf(v.y, 0.f);
                v.z = fmaxf(v.z, 0.f); v.w = fmaxf(v.w, 0.f);
            }
            *(float4*)(C + (size_t)gm * ldc + gn) = v;
        }
    }
}

// ---------------- launch ----------------
extern "C" void kernel_launch(void* const* d_in, const int* in_sizes, int n_in,
                              void* d_out, int out_size) {
    const float* x  = (const float*)d_in[0];
    const void*  ei = d_in[1];                 // int32 or int64, detected on device
    const float* ew = (const float*)d_in[2];
    const float* W1 = (const float*)d_in[3];
    const float* b1 = (const float*)d_in[4];
    const float* W2 = (const float*)d_in[5];
    const float* b2 = (const float*)d_in[6];
    float* out = (float*)d_out;

    int N = in_sizes[0] / IN_C;   // 100000
    int E = in_sizes[2];          // 3200000
    if (N > NN) N = NN;
    if (E > EE) E = EE;

    int *row, *col, *flag, *cnt, *rowptr, *cursor, *bsum, *pcol;
    float *deg, *pnw, *tx1, *s, *h, *z, *u, *w1c, *w2c;
    cudaGetSymbolAddress((void**)&row,    g_row);
    cudaGetSymbolAddress((void**)&col,    g_col);
    cudaGetSymbolAddress((void**)&flag,   g_is64);
    cudaGetSymbolAddress((void**)&cnt,    g_cnt);
    cudaGetSymbolAddress((void**)&rowptr, g_rowptr);
    cudaGetSymbolAddress((void**)&cursor, g_cursor);
    cudaGetSymbolAddress((void**)&bsum,   g_bsum);
    cudaGetSymbolAddress((void**)&pcol,   g_pcol);
    cudaGetSymbolAddress((void**)&deg,    g_deg);
    cudaGetSymbolAddress((void**)&pnw,    g_pnw);
    cudaGetSymbolAddress((void**)&tx1,    g_tx1);
    cudaGetSymbolAddress((void**)&s,      g_s);
    cudaGetSymbolAddress((void**)&h,      g_h);
    cudaGetSymbolAddress((void**)&z,      g_z);
    cudaGetSymbolAddress((void**)&u,      g_u);
    cudaGetSymbolAddress((void**)&w1c,    g_w1c);
    cudaGetSymbolAddress((void**)&w2c,    g_w2c);

    cudaMemsetAsync(deg, 0, (size_t)N * sizeof(float), 0);
    cudaMemsetAsync(cnt, 0, (size_t)N * sizeof(int), 0);

    const int T = 256;
    const int nb = (N + SCAN_B - 1) / SCAN_B;

    // edge index dtype detection + conversion to int32
    k_detect<<<1, 1>>>(ei, E, N, flag);
    k_cvt<<<(E + T - 1) / T, T>>>(ei, E, flag, row, col);

    // degrees + normalization
    k_deg2<<<(E + T - 1) / T, T>>>(row, ew, deg, cnt, E);
    k_dinv<<<(N + T - 1) / T, T>>>(deg, N);

    // CSR build
    k_scan1<<<nb, SCAN_B>>>(cnt, rowptr, bsum, N);
    k_scan2<<<1, NB_MAX>>>(bsum, nb);
    k_scan3<<<nb, SCAN_B>>>(rowptr, cursor, bsum, N);
    k_scatter<<<(E + T - 1) / T, T>>>(row, col, ew, deg, cursor, pcol, pnw, E);

    // weight folding
    k_w1c<<<(3 * IN_C * HID_C + T - 1) / T, T>>>(W1, w1c);
    k_w2c<<<(HID_C * 3 * OUT_C + T - 1) / T, T>>>(W2, w2c);

    const int spmmBlocks = (N * 32 + T - 1) / T;   // one warp per row

    // Layer 1 Chebyshev terms
    spmm_csr128<<<spmmBlocks, T>>>(rowptr, cnt, pcol, pnw, x,   IN_C / 4, 0, tx1, IN_C / 4, N);
    spmm_csr128<<<spmmBlocks, T>>>(rowptr, cnt, pcol, pnw, tx1, IN_C / 4, 0, s,   IN_C / 4, N);

    // h = relu([x|tx1|s] @ w1c + b1)
    {
        dim3 grid((N + BM - 1) / BM, HID_C / BN);
        gemm_kernel<<<grid, GEMM_THREADS>>>(x, tx1, s, IN_C, IN_C,
                                            w1c, HID_C, h, HID_C, b1,
                                            N, HID_C, 3 * IN_C, 1);
    }

    // z = h @ w2c   [N,192]
    {
        dim3 grid((N + BM - 1) / BM, (3 * OUT_C) / BN);
        gemm_kernel<<<grid, GEMM_THREADS>>>(h, h, h, HID_C, HID_C,
                                            w2c, 3 * OUT_C, z, 3 * OUT_C, nullptr,
                                            N, 3 * OUT_C, HID_C, 0);
    }

    // u = L [z1|z2]  (cols 64..191 of z)
    spmm_csr128<<<spmmBlocks, T>>>(rowptr, cnt, pcol, pnw, z, 48, 16, u, 32, N);

    // out = z0 - z2 + u_lo + b2 + 2*L(u_hi)   (fully fused, writes every row once)
    spmm_csr64_final<<<spmmBlocks, T>>>(rowptr, cnt, pcol, pnw, u, z, b2, out, N);
}

// round 7
// speedup vs baseline: 3.2954x; 1.3712x over previous
#include <cuda_runtime.h>
#include <cuda_bf16.h>
#include <stdint.h>

// Problem constants (dataset-fixed; scratch arrays sized to these)
#define NN 100000
#define EE 3200000
#define IN_C 128
#define HID_C 256
#define OUT_C 64
#define SCAN_B 256
#define NB_MAX 512   // ceil(NN/SCAN_B) = 391 <= 512

// ---------------- device scratch (no dynamic allocation allowed) ----------------
__device__ int   g_row[EE];
__device__ int   g_col[EE];
__device__ int   g_is64[1];
__device__ float g_deg[NN];
__device__ int   g_cnt[NN];
__device__ int   g_rowptr[NN];
__device__ int   g_cursor[NN];
__device__ int   g_bsum[NB_MAX];
__device__ int   g_pcol[EE];
__device__ float g_pnw[EE];
__device__ float g_tx1[NN * IN_C];          // L x              [N,128]
__device__ float g_s[NN * IN_C];            // L (L x)          [N,128]
__device__ float g_z[NN * 3 * OUT_C];       // [N,192] fp32
__device__ float g_u[NN * 2 * OUT_C];       // [N,128] fp32
__device__ __nv_bfloat16 g_w1t_hi[384 * 256];   // k-major folded layer-1 W [K,ch]
__device__ __nv_bfloat16 g_w1t_lo[384 * 256];
__device__ __nv_bfloat16 g_w2t_hi[256 * 256];   // k-major layer-2 W [K,ch] (192 used, padded)
__device__ __nv_bfloat16 g_w2t_lo[256 * 256];
__device__ __nv_bfloat16 g_hhi[(size_t)NN * 256];  // h split hi [N,256]
__device__ __nv_bfloat16 g_hlo[(size_t)NN * 256];  // h split lo

// ---------------- helpers ----------------
__device__ __forceinline__ uint32_t sm_u32(const void* p) {
    uint32_t a;
    asm("{ .reg .u64 t; cvta.to.shared.u64 t, %1; cvt.u32.u64 %0, t; }" : "=r"(a) : "l"(p));
    return a;
}
__device__ __forceinline__ uint32_t b2u(__nv_bfloat162 v) {
    return *reinterpret_cast<uint32_t*>(&v);
}
// split 8 fp32 -> 8 bf16 hi + 8 bf16 lo (packed)
__device__ __forceinline__ void cvt8(float4 a, float4 b, uint4& hv, uint4& lv) {
    __nv_bfloat162 h0 = __floats2bfloat162_rn(a.x, a.y);
    __nv_bfloat162 h1 = __floats2bfloat162_rn(a.z, a.w);
    __nv_bfloat162 h2 = __floats2bfloat162_rn(b.x, b.y);
    __nv_bfloat162 h3 = __floats2bfloat162_rn(b.z, b.w);
    __nv_bfloat162 l0 = __floats2bfloat162_rn(a.x - __bfloat162float(h0.x), a.y - __bfloat162float(h0.y));
    __nv_bfloat162 l1 = __floats2bfloat162_rn(a.z - __bfloat162float(h1.x), a.w - __bfloat162float(h1.y));
    __nv_bfloat162 l2 = __floats2bfloat162_rn(b.x - __bfloat162float(h2.x), b.y - __bfloat162float(h2.y));
    __nv_bfloat162 l3 = __floats2bfloat162_rn(b.z - __bfloat162float(h3.x), b.w - __bfloat162float(h3.y));
    hv = make_uint4(b2u(h0), b2u(h1), b2u(h2), b2u(h3));
    lv = make_uint4(b2u(l0), b2u(l1), b2u(l2), b2u(l3));
}

// mma.sync bf16 (sm_80+, works on base sm_100 target)
__device__ __forceinline__ void mma_bf16(float* d, const uint32_t* a, const uint32_t* b) {
    asm volatile(
        "mma.sync.aligned.m16n8k16.row.col.f32.bf16.bf16.f32 "
        "{%0,%1,%2,%3}, {%4,%5,%6,%7}, {%8,%9}, {%0,%1,%2,%3};"
        : "+f"(d[0]), "+f"(d[1]), "+f"(d[2]), "+f"(d[3])
        : "r"(a[0]), "r"(a[1]), "r"(a[2]), "r"(a[3]), "r"(b[0]), "r"(b[1]));
}
__device__ __forceinline__ void ldsm_x4(uint32_t* r, uint32_t addr) {
    asm volatile("ldmatrix.sync.aligned.m8n8.x4.shared.b16 {%0,%1,%2,%3}, [%4];"
                 : "=r"(r[0]), "=r"(r[1]), "=r"(r[2]), "=r"(r[3]) : "r"(addr));
}
__device__ __forceinline__ void ldsm_x2t(uint32_t* r, uint32_t addr) {
    asm volatile("ldmatrix.sync.aligned.m8n8.x2.trans.shared.b16 {%0,%1}, [%2];"
                 : "=r"(r[0]), "=r"(r[1]) : "r"(addr));
}

// smem layout (static): A 128x(32+8)bf16 hi/lo, B 32x(128+8)bf16 hi/lo
#define A_STR 80     // bytes per A row
#define B_STR 272    // bytes per B row
#define OFF_AH 0
#define OFF_AL 10240
#define OFF_BH 20480
#define OFF_BL 29184
#define SM_BYTES 37888

// ---------------- edge index dtype detection + conversion ----------------
__global__ void k_detect(const void* ei, int E, int n, int* flag) {
    const long long* p = (const long long*)ei;
    int cnt = E < 1024 ? E : 1024;
    int ok64 = 1;
    for (int i = 0; i < cnt; i++) {
        long long v = p[i];
        if (v < 0 || v >= n) { ok64 = 0; break; }
    }
    flag[0] = ok64;
}

__global__ void k_cvt(const void* ei, int E, const int* flag,
                      int* __restrict__ row, int* __restrict__ col) {
    int e = blockIdx.x * blockDim.x + threadIdx.x;
    if (e >= E) return;
    if (flag[0]) {
        const long long* p = (const long long*)ei;
        row[e] = (int)p[e];
        col[e] = (int)p[(long long)E + e];
    } else {
        const int* p = (const int*)ei;
        row[e] = p[e];
        col[e] = p[E + e];
    }
}

// ---------------- graph preprocessing ----------------
__global__ void k_deg2(const int* __restrict__ row, const float* __restrict__ w,
                       float* __restrict__ deg, int* __restrict__ cnt, int E) {
    int e = blockIdx.x * blockDim.x + threadIdx.x;
    if (e < E) {
        int r = row[e];
        atomicAdd(&deg[r], w[e]);
        atomicAdd(&cnt[r], 1);
    }
}

__global__ void k_dinv(float* __restrict__ deg, int n) {
    int i = blockIdx.x * blockDim.x + threadIdx.x;
    if (i < n) {
        float d = deg[i];
        deg[i] = (d > 0.0f) ? rsqrtf(d) : 0.0f;
    }
}

__global__ void k_scan1(const int* __restrict__ cnt, int* __restrict__ rowptr,
                        int* __restrict__ bsum, int n) {
    __shared__ int sm[SCAN_B];
    int t = threadIdx.x;
    int i = blockIdx.x * SCAN_B + t;
    int v = (i < n) ? cnt[i] : 0;
    int orig = v;
#pragma unroll
    for (int d = 1; d < SCAN_B; d <<= 1) {
        sm[t] = v; __syncthreads();
        int a = (t >= d) ? sm[t - d] : 0; __syncthreads();
        v += a;
    }
    if (i < n) rowptr[i] = v - orig;
    if (t == SCAN_B - 1) bsum[blockIdx.x] = v;
}

__global__ void k_scan2(int* __restrict__ bsum, int nb) {
    __shared__ int sm[NB_MAX];
    int t = threadIdx.x;
    int v = (t < nb) ? bsum[t] : 0;
    int orig = v;
#pragma unroll
    for (int d = 1; d < NB_MAX; d <<= 1) {
        sm[t] = v; __syncthreads();
        int a = (t >= d) ? sm[t - d] : 0; __syncthreads();
        v += a;
    }
    if (t < nb) bsum[t] = v - orig;
}

__global__ void k_scan3(int* __restrict__ rowptr, int* __restrict__ cursor,
                        const int* __restrict__ bsum, int n) {
    int i = blockIdx.x * SCAN_B + threadIdx.x;
    if (i < n) {
        int v = rowptr[i] + bsum[blockIdx.x];
        rowptr[i] = v;
        cursor[i] = v;
    }
}

__global__ void k_scatter(const int* __restrict__ row, const int* __restrict__ col,
                          const float* __restrict__ w, const float* __restrict__ dinv,
                          int* __restrict__ cursor,
                          int* __restrict__ pcol, float* __restrict__ pnw, int E) {
    int e = blockIdx.x * blockDim.x + threadIdx.x;
    if (e >= E) return;
    int r = row[e];
    int c = col[e];
    int pos = atomicAdd(&cursor[r], 1);
    pcol[pos] = c;
    pnw[pos] = -(dinv[r] * w[e] * dinv[c]);
}

// ---------------- weight prep: fold + k-major + bf16 split ----------------
// w1t[k][ch], k in [0,384): p=k/128, r=k%128
//   p=0: W1[0][r][ch]-W1[2][r][ch]; p=1: W1[1][r][ch]; p=2: 2*W1[2][r][ch]
__global__ void k_w1t(const float* __restrict__ W1,
                      __nv_bfloat16* __restrict__ whi, __nv_bfloat16* __restrict__ wlo) {
    int i = blockIdx.x * blockDim.x + threadIdx.x;
    const int total = 384 * 256;
    if (i >= total) return;
    int k = i / 256;
    int ch = i - k * 256;
    int p = k >> 7, r = k & 127;
    float f;
    if (p == 0)      f = W1[r * 256 + ch] - W1[2 * 32768 + r * 256 + ch];
    else if (p == 1) f = W1[32768 + r * 256 + ch];
    else             f = 2.0f * W1[2 * 32768 + r * 256 + ch];
    __nv_bfloat16 h = __float2bfloat16(f);
    whi[i] = h;
    wlo[i] = __float2bfloat16(f - __bfloat162float(h));
}

// w2t[k][ch] (ch 192..255 zero): f = W2[ch/64][k][ch%64];  W2 is [3][256][64]
__global__ void k_w2t(const float* __restrict__ W2,
                      __nv_bfloat16* __restrict__ whi, __nv_bfloat16* __restrict__ wlo) {
    int i = blockIdx.x * blockDim.x + threadIdx.x;
    const int total = 256 * 256;
    if (i >= total) return;
    int k = i / 256;
    int ch = i - k * 256;
    float f = 0.0f;
    if (ch < 192) f = W2[(ch / 64) * 16384 + k * 64 + (ch % 64)];
    __nv_bfloat16 h = __float2bfloat16(f);
    whi[i] = h;
    wlo[i] = __float2bfloat16(f - __bfloat162float(h));
}

// ---------------- CSR SpMM (proven R5 path) ----------------
__global__ void spmm_csr128(const int* __restrict__ rowptr, const int* __restrict__ cnt,
                            const int* __restrict__ pcol, const float* __restrict__ pnw,
                            const float* __restrict__ src, int sstride4, int soff4,
                            float* __restrict__ dst, int dstride4, int N) {
    int r = (blockIdx.x * blockDim.x + threadIdx.x) >> 5;
    int lane = threadIdx.x & 31;
    if (r >= N) return;
    int e = rowptr[r];
    int end = e + cnt[r];
    float4 acc = make_float4(0.f, 0.f, 0.f, 0.f);
    const float4* s4 = (const float4*)src;
    for (; e + 1 < end; e += 2) {
        int c0 = __ldg(&pcol[e]);     float n0 = __ldg(&pnw[e]);
        int c1 = __ldg(&pcol[e + 1]); float n1 = __ldg(&pnw[e + 1]);
        float4 v0 = __ldg(&s4[(size_t)c0 * sstride4 + soff4 + lane]);
        float4 v1 = __ldg(&s4[(size_t)c1 * sstride4 + soff4 + lane]);
        acc.x = fmaf(n0, v0.x, acc.x); acc.y = fmaf(n0, v0.y, acc.y);
        acc.z = fmaf(n0, v0.z, acc.z); acc.w = fmaf(n0, v0.w, acc.w);
        acc.x = fmaf(n1, v1.x, acc.x); acc.y = fmaf(n1, v1.y, acc.y);
        acc.z = fmaf(n1, v1.z, acc.z); acc.w = fmaf(n1, v1.w, acc.w);
    }
    if (e < end) {
        int c0 = __ldg(&pcol[e]); float n0 = __ldg(&pnw[e]);
        float4 v0 = __ldg(&s4[(size_t)c0 * sstride4 + soff4 + lane]);
        acc.x = fmaf(n0, v0.x, acc.x); acc.y = fmaf(n0, v0.y, acc.y);
        acc.z = fmaf(n0, v0.z, acc.z); acc.w = fmaf(n0, v0.w, acc.w);
    }
    ((float4*)dst)[(size_t)r * dstride4 + lane] = acc;
}

__global__ void spmm_csr64_final(const int* __restrict__ rowptr, const int* __restrict__ cnt,
                                 const int* __restrict__ pcol, const float* __restrict__ pnw,
                                 const float* __restrict__ u, const float* __restrict__ z,
                                 const float* __restrict__ b2,
                                 float* __restrict__ out, int N) {
    int r = (blockIdx.x * blockDim.x + threadIdx.x) >> 5;
    int lane = threadIdx.x & 31;
    if (r >= N) return;
    int e = rowptr[r];
    int end = e + cnt[r];
    float2 acc = make_float2(0.f, 0.f);
    for (; e + 1 < end; e += 2) {
        int c0 = __ldg(&pcol[e]);     float n0 = __ldg(&pnw[e]);
        int c1 = __ldg(&pcol[e + 1]); float n1 = __ldg(&pnw[e + 1]);
        float2 v0 = __ldg((const float2*)(u + (size_t)c0 * 128 + 64 + lane * 2));
        float2 v1 = __ldg((const float2*)(u + (size_t)c1 * 128 + 64 + lane * 2));
        acc.x = fmaf(n0, v0.x, acc.x); acc.y = fmaf(n0, v0.y, acc.y);
        acc.x = fmaf(n1, v1.x, acc.x); acc.y = fmaf(n1, v1.y, acc.y);
    }
    if (e < end) {
        int c0 = __ldg(&pcol[e]); float n0 = __ldg(&pnw[e]);
        float2 v0 = __ldg((const float2*)(u + (size_t)c0 * 128 + 64 + lane * 2));
        acc.x = fmaf(n0, v0.x, acc.x); acc.y = fmaf(n0, v0.y, acc.y);
    }
    int o = lane * 2;
    float2 z0 = *(const float2*)(z + (size_t)r * 192 + o);
    float2 z2 = *(const float2*)(z + (size_t)r * 192 + 128 + o);
    float2 ul = *(const float2*)(u + (size_t)r * 128 + o);
    float2 bb = *(const float2*)(b2 + o);
    float2 res;
    res.x = z0.x - z2.x + ul.x + bb.x + 2.0f * acc.x;
    res.y = z0.y - z2.y + ul.y + bb.y + 2.0f * acc.y;
    *(float2*)(out + (size_t)r * 64 + o) = res;
}

// ---------------- mma.sync GEMM core (shared by both GEMMs) ----------------
// Computes 128x128 tile: acc[mt][nt][4] for warp layout wm=wid&3 (32 rows), wn=wid>>2 (64 cols).
__device__ __forceinline__ void gemm_tile_mma(
    char* sm, uint32_t sbase, int wm, int wn, int lane, float acc[2][8][4]) {
    uint32_t aH = sbase + OFF_AH, aL = sbase + OFF_AL;
    uint32_t bH = sbase + OFF_BH, bL = sbase + OFF_BL;
#pragma unroll
    for (int ks = 0; ks < 2; ks++) {
        uint32_t ah[2][4], al[2][4];
#pragma unroll
        for (int mt = 0; mt < 2; mt++) {
            uint32_t ro = (uint32_t)(wm * 32 + mt * 16 + (lane & 15)) * A_STR + ks * 32 + (lane >> 4) * 16;
            ldsm_x4(ah[mt], aH + ro);
            ldsm_x4(al[mt], aL + ro);
        }
#pragma unroll
        for (int nt = 0; nt < 8; nt++) {
            uint32_t bo = (uint32_t)(ks * 16 + (lane & 15)) * B_STR + (wn * 64 + nt * 8) * 2;
            uint32_t bh[2], bl[2];
            ldsm_x2t(bh, bH + bo);
            ldsm_x2t(bl, bL + bo);
#pragma unroll
            for (int mt = 0; mt < 2; mt++) {
                mma_bf16(acc[mt][nt], ah[mt], bh);
                mma_bf16(acc[mt][nt], al[mt], bh);
                mma_bf16(acc[mt][nt], ah[mt], bl);
            }
        }
    }
}

// load B chunk (32 x 128 bf16 hi/lo) from k-major split weights [K][256]
__device__ __forceinline__ void load_B(char* sm, const __nv_bfloat16* whi,
                                       const __nv_bfloat16* wlo, int k0, int chbase, int tid) {
    int brow = tid >> 3, bc = (tid & 7) * 16;
    const uint4* ph = (const uint4*)(whi + (size_t)(k0 + brow) * 256 + chbase + bc);
    const uint4* pl = (const uint4*)(wlo + (size_t)(k0 + brow) * 256 + chbase + bc);
    char* dh = sm + OFF_BH + brow * B_STR + bc * 2;
    char* dl = sm + OFF_BL + brow * B_STR + bc * 2;
    *(uint4*)(dh)      = __ldg(&ph[0]);
    *(uint4*)(dh + 16) = __ldg(&ph[1]);
    *(uint4*)(dl)      = __ldg(&pl[0]);
    *(uint4*)(dl + 16) = __ldg(&pl[1]);
}

// ---------------- GEMM1: h = relu([x|tx1|s] @ w1 + b1) -> split bf16 ----------------
__global__ __launch_bounds__(256)
void gemm1_mma(const float* __restrict__ x, const float* __restrict__ tx1,
               const float* __restrict__ s,
               const __nv_bfloat16* __restrict__ whi, const __nv_bfloat16* __restrict__ wlo,
               const float* __restrict__ b1,
               __nv_bfloat16* __restrict__ hhi, __nv_bfloat16* __restrict__ hlo, int N) {
    __shared__ __align__(16) char sm[SM_BYTES];
    uint32_t sbase = sm_u32(sm);
    int tid = threadIdx.x, wid = tid >> 5, lane = tid & 31;
    int wm = wid & 3, wn = wid >> 2;
    int n0 = blockIdx.x * 128, chbase = blockIdx.y * 128;

    float acc[2][8][4];
#pragma unroll
    for (int i = 0; i < 2; i++)
#pragma unroll
        for (int j = 0; j < 8; j++)
#pragma unroll
            for (int q = 0; q < 4; q++) acc[i][j][q] = 0.f;

    for (int kc = 0; kc < 12; kc++) {
        int part = kc >> 2, kloc = (kc & 3) * 32, k0 = kc * 32;
        const float* sp = (part == 0) ? x : ((part == 1) ? tx1 : s);
        // A: 128 rows x 32 fp32 -> split bf16
        {
            int row = tid >> 1, cb = (tid & 1) * 16;
            char* dh = sm + OFF_AH + row * A_STR + cb * 2;
            char* dl = sm + OFF_AL + row * A_STR + cb * 2;
            if (n0 + row < N) {
                const float4* p = (const float4*)(sp + (size_t)(n0 + row) * 128 + kloc + cb);
                float4 a = __ldg(&p[0]), b = __ldg(&p[1]), c = __ldg(&p[2]), d = __ldg(&p[3]);
                uint4 h0, l0, h1, l1;
                cvt8(a, b, h0, l0);
                cvt8(c, d, h1, l1);
                *(uint4*)(dh) = h0; *(uint4*)(dh + 16) = h1;
                *(uint4*)(dl) = l0; *(uint4*)(dl + 16) = l1;
            } else {
                uint4 zz = make_uint4(0, 0, 0, 0);
                *(uint4*)(dh) = zz; *(uint4*)(dh + 16) = zz;
                *(uint4*)(dl) = zz; *(uint4*)(dl + 16) = zz;
            }
        }
        load_B(sm, whi, wlo, k0, chbase, tid);
        __syncthreads();
        gemm_tile_mma(sm, sbase, wm, wn, lane, acc);
        __syncthreads();
    }

    // epilogue: bias + relu + split -> hhi/hlo [n][256]
    int r = lane >> 2, cq = (lane & 3) * 2;
#pragma unroll
    for (int nt = 0; nt < 8; nt++) {
        int ch = chbase + wn * 64 + nt * 8 + cq;
        float bi0 = __ldg(&b1[ch]), bi1 = __ldg(&b1[ch + 1]);
#pragma unroll
        for (int mt = 0; mt < 2; mt++) {
            int nr = n0 + wm * 32 + mt * 16 + r;
#pragma unroll
            for (int half = 0; half < 2; half++) {
                int n = nr + half * 8;
                if (n < N) {
                    float v0 = fmaxf(acc[mt][nt][half * 2 + 0] + bi0, 0.f);
                    float v1 = fmaxf(acc[mt][nt][half * 2 + 1] + bi1, 0.f);
                    __nv_bfloat162 h = __floats2bfloat162_rn(v0, v1);
                    __nv_bfloat162 l = __floats2bfloat162_rn(v0 - __bfloat162float(h.x),
                                                             v1 - __bfloat162float(h.y));
                    *(uint32_t*)(hhi + (size_t)n * 256 + ch) = b2u(h);
                    *(uint32_t*)(hlo + (size_t)n * 256 + ch) = b2u(l);
                }
            }
        }
    }
}

// ---------------- GEMM2: z = h @ w2 (fp32 out [N,192]) ----------------
__global__ __launch_bounds__(256)
void gemm2_mma(const __nv_bfloat16* __restrict__ hhi, const __nv_bfloat16* __restrict__ hlo,
               const __nv_bfloat16* __restrict__ whi, const __nv_bfloat16* __restrict__ wlo,
               float* __restrict__ z, int N) {
    __shared__ __align__(16) char sm[SM_BYTES];
    uint32_t sbase = sm_u32(sm);
    int tid = threadIdx.x, wid = tid >> 5, lane = tid & 31;
    int wm = wid & 3, wn = wid >> 2;
    int n0 = blockIdx.x * 128, chbase = blockIdx.y * 128;

    float acc[2][8][4];
#pragma unroll
    for (int i = 0; i < 2; i++)
#pragma unroll
        for (int j = 0; j < 8; j++)
#pragma unroll
            for (int q = 0; q < 4; q++) acc[i][j][q] = 0.f;

    for (int kc = 0; kc < 8; kc++) {
        int k0 = kc * 32;
        {
            int row = tid >> 1, cb = (tid & 1) * 16;
            char* dh = sm + OFF_AH + row * A_STR + cb * 2;
            char* dl = sm + OFF_AL + row * A_STR + cb * 2;
            if (n0 + row < N) {
                const uint4* ph = (const uint4*)(hhi + (size_t)(n0 + row) * 256 + k0 + cb);
                const uint4* pl = (const uint4*)(hlo + (size_t)(n0 + row) * 256 + k0 + cb);
                *(uint4*)(dh) = __ldg(&ph[0]); *(uint4*)(dh + 16) = __ldg(&ph[1]);
                *(uint4*)(dl) = __ldg(&pl[0]); *(uint4*)(dl + 16) = __ldg(&pl[1]);
            } else {
                uint4 zz = make_uint4(0, 0, 0, 0);
                *(uint4*)(dh) = zz; *(uint4*)(dh + 16) = zz;
                *(uint4*)(dl) = zz; *(uint4*)(dl + 16) = zz;
            }
        }
        load_B(sm, whi, wlo, k0, chbase, tid);
        __syncthreads();
        gemm_tile_mma(sm, sbase, wm, wn, lane, acc);
        __syncthreads();
    }

    int r = lane >> 2, cq = (lane & 3) * 2;
#pragma unroll
    for (int nt = 0; nt < 8; nt++) {
        int ch = chbase + wn * 64 + nt * 8 + cq;
        if (ch < 192) {
#pragma unroll
            for (int mt = 0; mt < 2; mt++) {
                int nr = n0 + wm * 32 + mt * 16 + r;
#pragma unroll
                for (int half = 0; half < 2; half++) {
                    int n = nr + half * 8;
                    if (n < N) {
                        float2 v = make_float2(acc[mt][nt][half * 2 + 0],
                                               acc[mt][nt][half * 2 + 1]);
                        *(float2*)(z + (size_t)n * 192 + ch) = v;
                    }
                }
            }
        }
    }
}

// ---------------- launch ----------------
extern "C" void kernel_launch(void* const* d_in, const int* in_sizes, int n_in,
                              void* d_out, int out_size) {
    const float* x  = (const float*)d_in[0];
    const void*  ei = d_in[1];
    const float* ew = (const float*)d_in[2];
    const float* W1 = (const float*)d_in[3];
    const float* b1 = (const float*)d_in[4];
    const float* W2 = (const float*)d_in[5];
    const float* b2 = (const float*)d_in[6];
    float* out = (float*)d_out;

    int N = in_sizes[0] / IN_C;
    int E = in_sizes[2];
    if (N > NN) N = NN;
    if (E > EE) E = EE;

    int *row, *col, *flag, *cnt, *rowptr, *cursor, *bsum, *pcol;
    float *deg, *pnw, *tx1, *s, *z, *u;
    __nv_bfloat16 *w1hi, *w1lo, *w2hi, *w2lo, *hhi, *hlo;
    cudaGetSymbolAddress((void**)&row,    g_row);
    cudaGetSymbolAddress((void**)&col,    g_col);
    cudaGetSymbolAddress((void**)&flag,   g_is64);
    cudaGetSymbolAddress((void**)&cnt,    g_cnt);
    cudaGetSymbolAddress((void**)&rowptr, g_rowptr);
    cudaGetSymbolAddress((void**)&cursor, g_cursor);
    cudaGetSymbolAddress((void**)&bsum,   g_bsum);
    cudaGetSymbolAddress((void**)&pcol,   g_pcol);
    cudaGetSymbolAddress((void**)&deg,    g_deg);
    cudaGetSymbolAddress((void**)&pnw,    g_pnw);
    cudaGetSymbolAddress((void**)&tx1,    g_tx1);
    cudaGetSymbolAddress((void**)&s,      g_s);
    cudaGetSymbolAddress((void**)&z,      g_z);
    cudaGetSymbolAddress((void**)&u,      g_u);
    cudaGetSymbolAddress((void**)&w1hi,   g_w1t_hi);
    cudaGetSymbolAddress((void**)&w1lo,   g_w1t_lo);
    cudaGetSymbolAddress((void**)&w2hi,   g_w2t_hi);
    cudaGetSymbolAddress((void**)&w2lo,   g_w2t_lo);
    cudaGetSymbolAddress((void**)&hhi,    g_hhi);
    cudaGetSymbolAddress((void**)&hlo,    g_hlo);

    cudaMemsetAsync(deg, 0, (size_t)N * sizeof(float), 0);
    cudaMemsetAsync(cnt, 0, (size_t)N * sizeof(int), 0);

    const int T = 256;
    const int nb = (N + SCAN_B - 1) / SCAN_B;

    k_detect<<<1, 1>>>(ei, E, N, flag);
    k_cvt<<<(E + T - 1) / T, T>>>(ei, E, flag, row, col);

    k_deg2<<<(E + T - 1) / T, T>>>(row, ew, deg, cnt, E);
    k_dinv<<<(N + T - 1) / T, T>>>(deg, N);

    k_scan1<<<nb, SCAN_B>>>(cnt, rowptr, bsum, N);
    k_scan2<<<1, NB_MAX>>>(bsum, nb);
    k_scan3<<<nb, SCAN_B>>>(rowptr, cursor, bsum, N);
    k_scatter<<<(E + T - 1) / T, T>>>(row, col, ew, deg, cursor, pcol, pnw, E);

    k_w1t<<<(384 * 256 + T - 1) / T, T>>>(W1, w1hi, w1lo);
    k_w2t<<<(256 * 256 + T - 1) / T, T>>>(W2, w2hi, w2lo);

    const int spmmBlocks = (N * 32 + T - 1) / T;

    spmm_csr128<<<spmmBlocks, T>>>(rowptr, cnt, pcol, pnw, x,   IN_C / 4, 0, tx1, IN_C / 4, N);
    spmm_csr128<<<spmmBlocks, T>>>(rowptr, cnt, pcol, pnw, tx1, IN_C / 4, 0, s,   IN_C / 4, N);

    const int mtiles = (N + 127) / 128;
    gemm1_mma<<<dim3(mtiles, 2), 256>>>(x, tx1, s, w1hi, w1lo, b1, hhi, hlo, N);
    gemm2_mma<<<dim3(mtiles, 2), 256>>>(hhi, hlo, w2hi, w2lo, z, N);

    spmm_csr128<<<spmmBlocks, T>>>(rowptr, cnt, pcol, pnw, z, 48, 16, u, 32, N);
    spmm_csr64_final<<<spmmBlocks, T>>>(rowptr, cnt, pcol, pnw, u, z, b2, out, N);
}